// round 3
// baseline (speedup 1.0000x reference)
#include <cuda_runtime.h>
#include <cstdint>

#define BB    4
#define C_IN  32
#define C_OUT 64
#define EDGES 200000
#define KK    5

__device__ __align__(256) float g_xT[BB * EDGES * C_IN];

__device__ __forceinline__ unsigned long long pack2(float lo, float hi) {
    unsigned long long r;
    asm("mov.b64 %0, {%1, %2};" : "=l"(r) : "f"(lo), "f"(hi));
    return r;
}
__device__ __forceinline__ void unpack2(unsigned long long v, float& lo, float& hi) {
    asm("mov.b64 {%0, %1}, %2;" : "=f"(lo), "=f"(hi) : "l"(v));
}
__device__ __forceinline__ void fma2(unsigned long long& d,
                                     unsigned long long a,
                                     unsigned long long b) {
    asm("fma.rn.f32x2 %0, %1, %2, %0;" : "+l"(d) : "l"(a), "l"(b));
}

__global__ void transpose_x_kernel(const float* __restrict__ x) {
    __shared__ float tile[32][33];
    const int bb = blockIdx.y;
    const int e0 = blockIdx.x * 32;
    const int tx = threadIdx.x;
    const int ty = threadIdx.y;

    #pragma unroll
    for (int c = ty; c < C_IN; c += 8)
        tile[c][tx] = __ldg(&x[(bb * C_IN + c) * EDGES + e0 + tx]);
    __syncthreads();
    #pragma unroll
    for (int r = ty; r < 32; r += 8)
        g_xT[(size_t)(bb * EDGES + e0 + r) * C_IN + tx] = tile[tx][r];
}

__global__ void __launch_bounds__(128, 3)
mesh_conv_kernel(const int* __restrict__ Gi,
                 const float* __restrict__ Wsrc,
                 const float* __restrict__ bias,
                 float* __restrict__ out)
{
    __shared__ __align__(16) float Wsm[C_IN * KK * C_OUT];  // 40 KB
    __shared__ __align__(16) int   GiSm[128 * KK];          // 2.5 KB

    const int tid = threadIdx.x;
    const int bb  = blockIdx.y;
    const int e   = blockIdx.x * blockDim.x + tid;

    for (int i = tid; i < C_OUT * C_IN * KK; i += blockDim.x) {
        int o  = i / (C_IN * KK);
        int ck = i % (C_IN * KK);
        Wsm[ck * C_OUT + o] = __ldg(&Wsrc[i]);
    }

    // Stage Gi slice: base byte offset (bb*EDGES + blk*128)*20 is 16B-aligned.
    // Tail block covers only (EDGES - blk*128) rows -> clamp int4 count so we
    // never read past the Gi tensor.
    {
        const int rows    = min(128, EDGES - blockIdx.x * 128);
        const int n_int4  = (rows * KK) / 4;   // rows*5 ints; 64*5=320 -> 80, 128*5=640 -> 160
        const int4* gsrc = reinterpret_cast<const int4*>(
            Gi + ((size_t)bb * EDGES + (size_t)blockIdx.x * 128) * KK);
        int4* gdst = reinterpret_cast<int4*>(GiSm);
        for (int i = tid; i < n_int4; i += 128)
            gdst[i] = __ldg(&gsrc[i]);
    }
    __syncthreads();

    if (e >= EDGES) return;

    int idx[5];
    #pragma unroll
    for (int j = 0; j < 5; j++) idx[j] = GiSm[tid * KK + j];

    const float4* xb = reinterpret_cast<const float4*>(g_xT + (size_t)bb * EDGES * C_IN);

    unsigned long long acc[C_OUT / 2];
    #pragma unroll
    for (int o2 = 0; o2 < C_OUT / 2; o2++)
        acc[o2] = pack2(__ldg(&bias[2 * o2]), __ldg(&bias[2 * o2 + 1]));

    #pragma unroll 1
    for (int cb = 0; cb < C_IN / 8; cb++) {
        float f[5][8];
        #pragma unroll
        for (int j = 0; j < 5; j++) {
            float4 a  = xb[idx[j] * 8 + cb * 2];
            float4 bq = xb[idx[j] * 8 + cb * 2 + 1];
            f[j][0] = a.x;  f[j][1] = a.y;  f[j][2] = a.z;  f[j][3] = a.w;
            f[j][4] = bq.x; f[j][5] = bq.y; f[j][6] = bq.z; f[j][7] = bq.w;
        }

        #pragma unroll
        for (int cc = 0; cc < 8; cc++) {
            const int c = cb * 8 + cc;
            float g0 = f[0][cc];
            float s1 = f[1][cc] + f[3][cc];
            float s2 = f[2][cc] + f[4][cc];
            float d1 = fabsf(f[1][cc] - f[3][cc]);
            float d2 = fabsf(f[2][cc] - f[4][cc]);
            unsigned long long gp[5];
            gp[0] = pack2(g0, g0);
            gp[1] = pack2(s1, s1);
            gp[2] = pack2(s2, s2);
            gp[3] = pack2(d1, d1);
            gp[4] = pack2(d2, d2);

            #pragma unroll
            for (int k = 0; k < KK; k++) {
                const ulonglong2* wr = reinterpret_cast<const ulonglong2*>(
                    Wsm + (c * KK + k) * C_OUT);
                #pragma unroll
                for (int o4 = 0; o4 < C_OUT / 4; o4++) {
                    ulonglong2 w = wr[o4];          // broadcast LDS.128
                    fma2(acc[2 * o4],     gp[k], w.x);
                    fma2(acc[2 * o4 + 1], gp[k], w.y);
                }
            }
        }
    }

    float* outp = out + (size_t)bb * C_OUT * EDGES + e;
    #pragma unroll
    for (int o2 = 0; o2 < C_OUT / 2; o2++) {
        float lo, hi;
        unpack2(acc[o2], lo, hi);
        outp[0] = lo;
        outp += EDGES;
        outp[0] = hi;
        outp += EDGES;
    }
}

extern "C" void kernel_launch(void* const* d_in, const int* in_sizes, int n_in,
                              void* d_out, int out_size) {
    const float* x    = (const float*)d_in[0];
    const int*   Gi   = (const int*)  d_in[1];
    const float* W    = (const float*)d_in[2];
    const float* bias = (const float*)d_in[3];
    float*       out  = (float*)d_out;

    (void)in_sizes; (void)n_in; (void)out_size;

    dim3 tb(32, 8);
    dim3 tg(EDGES / 32, BB);
    transpose_x_kernel<<<tg, tb>>>(x);

    const int threads = 128;
    dim3 mg((EDGES + threads - 1) / threads, BB);
    mesh_conv_kernel<<<mg, threads>>>(Gi, W, bias, out);
}

// round 14
// speedup vs baseline: 1.7587x; 1.7587x over previous
#include <cuda_runtime.h>
#include <cstdint>

#define BB    4
#define C_IN  32
#define C_OUT 64
#define EDGES 200000
#define KK    5

// Transposed x: xT[b][e][c] (channel-contiguous 128B rows) — scratch.
__device__ __align__(256) float g_xT[BB * EDGES * C_IN];
// Staging for ck-major W before copy into constant bank.
__device__ __align__(16)  float g_Wt[C_IN * KK * C_OUT];

// W in the constant bank: 2560 ulonglong2 = 40 KB, warp-uniform access.
// c_W4[(c*KK + k)*16 + o4] = {(w[4o4],w[4o4+1]),(w[4o4+2],w[4o4+3])}
__constant__ __align__(16) ulonglong2 c_W4[C_IN * KK * C_OUT / 4];
__constant__ float c_bias[C_OUT];

// ---------------- packed f32x2 helpers ----------------
__device__ __forceinline__ unsigned long long pack2(float lo, float hi) {
    unsigned long long r;
    asm("mov.b64 %0, {%1, %2};" : "=l"(r) : "f"(lo), "f"(hi));
    return r;
}
__device__ __forceinline__ void unpack2(unsigned long long v, float& lo, float& hi) {
    asm("mov.b64 {%0, %1}, %2;" : "=f"(lo), "=f"(hi) : "l"(v));
}
// d = a * b + d  (packed 2x fp32 FMA — FFMA2 in SASS, 2x fp32 throughput)
__device__ __forceinline__ void fma2(unsigned long long& d,
                                     unsigned long long a,
                                     unsigned long long b) {
    asm("fma.rn.f32x2 %0, %1, %2, %0;" : "+l"(d) : "l"(a), "l"(b));
}

// ---------------- prep: W (64,32,1,5) o-major -> g_Wt ck-major ----------------
__global__ void prep_w_kernel(const float* __restrict__ Wsrc) {
    int i = blockIdx.x * blockDim.x + threadIdx.x;
    if (i < C_OUT * C_IN * KK) {
        int o  = i / (C_IN * KK);
        int ck = i % (C_IN * KK);
        g_Wt[ck * C_OUT + o] = __ldg(&Wsrc[i]);
    }
}

// ---------------- transpose: x (B,C,E) -> xT (B,E,C) ----------------
__global__ void transpose_x_kernel(const float* __restrict__ x) {
    __shared__ float tile[32][33];
    const int bb = blockIdx.y;
    const int e0 = blockIdx.x * 32;
    const int tx = threadIdx.x;
    const int ty = threadIdx.y;

    #pragma unroll
    for (int c = ty; c < C_IN; c += 8)
        tile[c][tx] = __ldg(&x[(bb * C_IN + c) * EDGES + e0 + tx]);
    __syncthreads();
    #pragma unroll
    for (int r = ty; r < 32; r += 8)
        g_xT[(size_t)(bb * EDGES + e0 + r) * C_IN + tx] = tile[tx][r];
}

// ---------------- main mesh-conv kernel ----------------
// TWO edges per thread: each const-bank W load feeds 4 FFMA2 (2 per edge),
// halving the W-operand stream per edge. Per-SM model (~84.5 2-edge warps/SM):
//   FMA: 10240 FFMA2/warp-slot x rt2 -> 433K cyc  <- binding
//   const port: 2560 LDC.128 x 2 cyc -> 432K (LDC) or ~54K (LDCU)
//   LSU: gathers + stores ~216K cyc
// -> ~240us kernel under either const-port outcome.
__global__ void __launch_bounds__(128, 2)
mesh_conv_kernel(const int* __restrict__ Gi,
                 float* __restrict__ out)          // (4,64,200000)
{
    __shared__ __align__(16) int GiSm[256 * KK];   // 5 KB

    const int tid    = threadIdx.x;
    const int bb     = blockIdx.y;
    const int base_e = blockIdx.x * 256;

    // Stage this block's Gi slice (up to 256 rows x 5 ints). Base byte offset
    // (bb*EDGES + base_e)*20 is a multiple of 16 (EDGES*20 and 256*20 are).
    // rows is 256 or 64 (tail): rows*5 divisible by 4 -> exact int4 count,
    // never reads past the Gi tensor.
    {
        const int rows   = min(256, EDGES - base_e);
        const int n_int4 = (rows * KK) / 4;       // 256 -> 320, 64 -> 80
        const int4* gsrc = reinterpret_cast<const int4*>(
            Gi + ((size_t)bb * EDGES + base_e) * KK);
        int4* gdst = reinterpret_cast<int4*>(GiSm);
        for (int i = tid; i < n_int4; i += 128)
            gdst[i] = __ldg(&gsrc[i]);
    }
    __syncthreads();

    const int eA = base_e + tid;
    const int eB = eA + 128;
    if (eA >= EDGES) return;                // no barriers after this point
    const bool hasB = (eB < EDGES);

    // Reference does xp=[0,x], idx=Gi+1 -> identical to direct x[:,Gi]
    // (Gi in [0,E); xp column 0 never selected).
    int idxA[5], idxB[5];
    #pragma unroll
    for (int j = 0; j < 5; j++) {
        idxA[j] = GiSm[tid * KK + j];
        idxB[j] = hasB ? GiSm[(tid + 128) * KK + j] : idxA[j];  // alias: in-bounds, result discarded
    }

    const float4* xb = reinterpret_cast<const float4*>(g_xT + (size_t)bb * EDGES * C_IN);
    // edge row i = xb + i*8 (32 floats = 8 float4); cb selects one float4.

    unsigned long long accA[C_OUT / 2], accB[C_OUT / 2];
    #pragma unroll
    for (int o2 = 0; o2 < C_OUT / 2; o2++) {
        unsigned long long bi = pack2(c_bias[2 * o2], c_bias[2 * o2 + 1]);
        accA[o2] = bi;
        accB[o2] = bi;
    }

    const ulonglong2* wptr = c_W4;  // walks all 2560 entries once, order (c,k,o4)

    #pragma unroll 1
    for (int cb = 0; cb < C_IN / 4; cb++) {   // 8 iterations, 4 channels each
        float4 fA[5], fB[5];
        #pragma unroll
        for (int j = 0; j < 5; j++) {
            fA[j] = xb[idxA[j] * 8 + cb];
            fB[j] = xb[idxB[j] * 8 + cb];
        }

        #pragma unroll
        for (int cc = 0; cc < 4; cc++) {
            const float a0 = (&fA[0].x)[cc], a1 = (&fA[1].x)[cc], a2 = (&fA[2].x)[cc],
                        a3 = (&fA[3].x)[cc], a4 = (&fA[4].x)[cc];
            const float b0 = (&fB[0].x)[cc], b1 = (&fB[1].x)[cc], b2 = (&fB[2].x)[cc],
                        b3 = (&fB[3].x)[cc], b4 = (&fB[4].x)[cc];

            const float sA1 = a1 + a3, sA2 = a2 + a4;
            const float dA1 = fabsf(a1 - a3), dA2 = fabsf(a2 - a4);
            const float sB1 = b1 + b3, sB2 = b2 + b4;
            const float dB1 = fabsf(b1 - b3), dB2 = fabsf(b2 - b4);

            unsigned long long gpA[5], gpB[5];
            gpA[0] = pack2(a0,  a0);
            gpA[1] = pack2(sA1, sA1);
            gpA[2] = pack2(sA2, sA2);
            gpA[3] = pack2(dA1, dA1);
            gpA[4] = pack2(dA2, dA2);
            gpB[0] = pack2(b0,  b0);
            gpB[1] = pack2(sB1, sB1);
            gpB[2] = pack2(sB2, sB2);
            gpB[3] = pack2(dB1, dB1);
            gpB[4] = pack2(dB2, dB2);

            #pragma unroll
            for (int k = 0; k < KK; k++) {
                #pragma unroll
                for (int o4 = 0; o4 < C_OUT / 4; o4++) {
                    ulonglong2 w = wptr[o4];       // const-port load, shared by 4 FMA2
                    fma2(accA[2 * o4],     gpA[k], w.x);
                    fma2(accA[2 * o4 + 1], gpA[k], w.y);
                    fma2(accB[2 * o4],     gpB[k], w.x);
                    fma2(accB[2 * o4 + 1], gpB[k], w.y);
                }
                wptr += C_OUT / 4;
            }
        }
    }

    // store: out[(bb*64 + o)*E + e]; lanes contiguous in e -> 128B coalesced.
    {
        float* outp = out + (size_t)bb * C_OUT * EDGES + eA;
        #pragma unroll
        for (int o2 = 0; o2 < C_OUT / 2; o2++) {
            float lo, hi;
            unpack2(accA[o2], lo, hi);
            outp[0] = lo; outp += EDGES;
            outp[0] = hi; outp += EDGES;
        }
    }
    if (hasB) {
        float* outp = out + (size_t)bb * C_OUT * EDGES + eB;
        #pragma unroll
        for (int o2 = 0; o2 < C_OUT / 2; o2++) {
            float lo, hi;
            unpack2(accB[o2], lo, hi);
            outp[0] = lo; outp += EDGES;
            outp[0] = hi; outp += EDGES;
        }
    }
}

extern "C" void kernel_launch(void* const* d_in, const int* in_sizes, int n_in,
                              void* d_out, int out_size) {
    const float* x    = (const float*)d_in[0];   // (4,32,200000)
    const int*   Gi   = (const int*)  d_in[1];   // (4,200000,5)
    const float* W    = (const float*)d_in[2];   // (64,32,1,5)
    const float* bias = (const float*)d_in[3];   // (64,)
    float*       out  = (float*)d_out;           // (4,64,200000,1)

    (void)in_sizes; (void)n_in; (void)out_size;

    // 1) W -> ck-major staging -> constant bank.
    //    BUG FIX (R12 evidence): in host code, the NAME of a __device__
    //    symbol (g_Wt) is a host-side shadow address, NOT a device pointer.
    //    Passing it as a D2D memcpy src silently failed, leaving c_W4 all
    //    zeros (measured rel_err 1.003 == bias-only output). Resolve the
    //    real device address with cudaGetSymbolAddress (pure query API:
    //    no allocation, no stream op, capture-safe).
    prep_w_kernel<<<(C_OUT * C_IN * KK + 255) / 256, 256>>>(W);
    void* wt_dev = nullptr;
    cudaGetSymbolAddress(&wt_dev, g_Wt);
    cudaMemcpyToSymbolAsync(c_W4, wt_dev, C_IN * KK * C_OUT * sizeof(float),
                            0, cudaMemcpyDeviceToDevice, 0);
    cudaMemcpyToSymbolAsync(c_bias, bias, C_OUT * sizeof(float),
                            0, cudaMemcpyDeviceToDevice, 0);

    // 2) transpose x -> xT[b][e][c]  (200000 % 32 == 0)
    dim3 tb(32, 8);
    dim3 tg(EDGES / 32, BB);
    transpose_x_kernel<<<tg, tb>>>(x);

    // 3) fused gather + symmetric combine + conv, 2 edges/thread
    dim3 mg((EDGES + 255) / 256, BB);
    mesh_conv_kernel<<<mg, 128>>>(Gi, out);
}